// round 2
// baseline (speedup 1.0000x reference)
#include <cuda_runtime.h>
#include <cuda_bf16.h>
#include <mma.h>
#include <math.h>

using namespace nvcuda;

// Problem dims
#define Bb   8192
#define Tt   8
#define Vv   65
#define Cc   512
#define Hh   8
#define HSs  64
#define Ll   6
#define DFFd 2048
#define NT   (Bb*Tt)   // 65536 tokens

// ---------------- scratch (device globals; no allocation allowed) ----------------
__device__ float g_x[(size_t)NT*Cc];          // activations            128 MB
__device__ float g_qkv[(size_t)NT*3*Cc];      // q|k|v per token        384 MB
__device__ float g_ao[(size_t)NT*Cc];         // attention output       128 MB
__device__ float g_y[(size_t)NT*Cc];          // gemm output (pre-LN)   128 MB
__device__ float g_h[(size_t)NT*DFFd];        // MLP hidden             512 MB
__device__ float g_wpack[(size_t)Ll*Cc*3*Cc]; // packed qkv weights      19 MB

// ---------------- weight repack: wq/wk/wv (L,H,C,HS) -> (L, C, 1536) row-major ----
__global__ void pack_qkv_kernel(const float* __restrict__ wq,
                                const float* __restrict__ wk,
                                const float* __restrict__ wv) {
    int i = blockIdx.x * 256 + threadIdx.x;           // over L*C*1536
    if (i >= Ll*Cc*3*Cc) return;
    int col = i % (3*Cc);
    int c   = (i / (3*Cc)) % Cc;
    int l   = i / (3*Cc*Cc);
    const float* src; int j;
    if (col < Cc)        { src = wq; j = col; }
    else if (col < 2*Cc) { src = wk; j = col - Cc; }
    else                 { src = wv; j = col - 2*Cc; }
    int h = j / HSs, d = j % HSs;
    g_wpack[i] = src[(((size_t)l*Hh + h)*Cc + c)*HSs + d];
}

// ---------------- embedding ----------------
__global__ void embed_kernel(const int* __restrict__ idx,
                             const float* __restrict__ tok,
                             const float* __restrict__ pos) {
    int i = blockIdx.x * 256 + threadIdx.x;           // over NT*C/4
    if (i >= NT*Cc/4) return;
    int c4 = i % (Cc/4);
    int token = i / (Cc/4);
    int t = token & (Tt-1);
    float4 a = ((const float4*)tok)[(size_t)idx[token]*(Cc/4) + c4];
    float4 p = ((const float4*)pos)[(size_t)t*(Cc/4) + c4];
    ((float4*)g_x)[i] = make_float4(a.x+p.x, a.y+p.y, a.z+p.z, a.w+p.w);
}

// ---------------- generic TF32 wmma GEMM: C = A(MxK) @ B(KxN) (+bias)(+relu) ------
// Requires M%128==0, N%128==0, K%32==0.
__global__ void __launch_bounds__(256, 2)
gemm_tf32(const float* __restrict__ A, const float* __restrict__ B,
          const float* __restrict__ bias, float* __restrict__ Cmat,
          int M, int N, int K, int relu)
{
    __shared__ float As[128][40];       // +8 pad
    __shared__ float Bs[32][136];       // +8 pad
    __shared__ float stage[8][16*16];   // per-warp epilogue staging (ldm=16, mult of 4)

    int tid  = threadIdx.x;
    int warp = tid >> 5, lane = tid & 31;
    int wm = warp >> 2, wn = warp & 3;  // 2x4 warp grid; warp tile 64x32
    int bm = blockIdx.y * 128, bn = blockIdx.x * 128;

    wmma::fragment<wmma::accumulator,16,16,8,float> acc[4][2];
    #pragma unroll
    for (int i = 0; i < 4; i++)
        #pragma unroll
        for (int j = 0; j < 2; j++)
            wmma::fill_fragment(acc[i][j], 0.0f);

    int arow = tid >> 3;     // 0..31 (stride 32: 4 passes cover 128 rows)
    int af4  = tid & 7;      // 8 float4 per 32-float row
    int brow = tid >> 5;     // 0..7 (stride 8: 4 passes cover 32 rows)
    int bf4  = tid & 31;     // 32 float4 per 128-float row

    for (int k0 = 0; k0 < K; k0 += 32) {
        #pragma unroll
        for (int r = 0; r < 4; r++) {
            int row = arow + 32*r;
            float4 v = *(const float4*)&A[(size_t)(bm+row)*K + k0 + af4*4];
            *(float4*)&As[row][af4*4] = v;
        }
        #pragma unroll
        for (int r = 0; r < 4; r++) {
            int row = brow + 8*r;
            float4 v = *(const float4*)&B[(size_t)(k0+row)*N + bn + bf4*4];
            *(float4*)&Bs[row][bf4*4] = v;
        }
        __syncthreads();
        #pragma unroll
        for (int kk = 0; kk < 4; kk++) {
            wmma::fragment<wmma::matrix_a,16,16,8,wmma::precision::tf32,wmma::row_major> af[4];
            wmma::fragment<wmma::matrix_b,16,16,8,wmma::precision::tf32,wmma::row_major> bf[2];
            #pragma unroll
            for (int i = 0; i < 4; i++) {
                wmma::load_matrix_sync(af[i], &As[wm*64 + i*16][kk*8], 40);
                #pragma unroll
                for (int t = 0; t < af[i].num_elements; t++)
                    af[i].x[t] = wmma::__float_to_tf32(af[i].x[t]);
            }
            #pragma unroll
            for (int j = 0; j < 2; j++) {
                wmma::load_matrix_sync(bf[j], &Bs[kk*8][wn*32 + j*16], 136);
                #pragma unroll
                for (int t = 0; t < bf[j].num_elements; t++)
                    bf[j].x[t] = wmma::__float_to_tf32(bf[j].x[t]);
            }
            #pragma unroll
            for (int i = 0; i < 4; i++)
                #pragma unroll
                for (int j = 0; j < 2; j++)
                    wmma::mma_sync(acc[i][j], af[i], bf[j], acc[i][j]);
        }
        __syncthreads();
    }

    // epilogue: stage each 16x16 frag through smem (ldm=16, legal), bias/relu, store
    #pragma unroll
    for (int i = 0; i < 4; i++) {
        #pragma unroll
        for (int j = 0; j < 2; j++) {
            wmma::store_matrix_sync(&stage[warp][0], acc[i][j], 16, wmma::mem_row_major);
            __syncwarp();
            int grow0 = bm + wm*64 + i*16;
            int gcol0 = bn + wn*32 + j*16;
            #pragma unroll
            for (int e = 0; e < 8; e++) {
                int idx2 = e*32 + lane;
                int r = idx2 >> 4, c = idx2 & 15;
                float v = stage[warp][r*16 + c];
                if (bias) v += bias[gcol0 + c];
                if (relu) v = fmaxf(v, 0.0f);
                Cmat[(size_t)(grow0 + r)*N + gcol0 + c] = v;
            }
            __syncwarp();
        }
    }
}

// ---------------- attention: one warp per (b,h); T=8, HS=64; scale = C^-0.5 -------
__global__ void __launch_bounds__(128)
attn_kernel() {
    __shared__ float sq[4][8][64], sk[4][8][64], sv[4][8][64];
    __shared__ float satt[4][8][8];
    int warp = threadIdx.x >> 5, lane = threadIdx.x & 31;
    int bh = blockIdx.x * 4 + warp;
    int b = bh >> 3, h = bh & 7;
    size_t tok0 = (size_t)b * Tt;

    #pragma unroll
    for (int t = 0; t < 8; t++) {
        const float* row = &g_qkv[(tok0 + t) * (3*Cc)];
        sq[warp][t][lane]    = row[h*64 + lane];
        sq[warp][t][lane+32] = row[h*64 + lane + 32];
        sk[warp][t][lane]    = row[Cc + h*64 + lane];
        sk[warp][t][lane+32] = row[Cc + h*64 + lane + 32];
        sv[warp][t][lane]    = row[2*Cc + h*64 + lane];
        sv[warp][t][lane+32] = row[2*Cc + h*64 + lane + 32];
    }
    __syncwarp();

    const float scale = 0.044194173824159216f;   // 512^-0.5  (reference uses C^-0.5)
    #pragma unroll
    for (int p = lane; p < 64; p += 32) {
        int t = p >> 3, s = p & 7;
        float acc = 0.f;
        #pragma unroll
        for (int d = 0; d < 64; d++) acc += sq[warp][t][d] * sk[warp][s][d];
        satt[warp][t][s] = (s <= t) ? acc * scale : 0.0f;   // masked entries handled below
    }
    __syncwarp();

    if (lane < 8) {
        int t = lane;
        float m = -1e30f;
        for (int s = 0; s <= t; s++) m = fmaxf(m, satt[warp][t][s]);
        float e[8]; float sum = 0.f;
        #pragma unroll
        for (int s = 0; s < 8; s++) {
            e[s] = (s <= t) ? __expf(satt[warp][t][s] - m) : 0.0f;
            sum += e[s];
        }
        float inv = 1.0f / sum;
        #pragma unroll
        for (int s = 0; s < 8; s++) satt[warp][t][s] = e[s] * inv;
    }
    __syncwarp();

    #pragma unroll
    for (int t = 0; t < 8; t++) {
        float a0 = 0.f, a1 = 0.f;
        #pragma unroll
        for (int s = 0; s < 8; s++) {
            float w = satt[warp][t][s];
            a0 += w * sv[warp][s][lane];
            a1 += w * sv[warp][s][lane + 32];
        }
        g_ao[(tok0 + t)*Cc + h*64 + lane]      = a0;
        g_ao[(tok0 + t)*Cc + h*64 + lane + 32] = a1;
    }
}

// ---------------- fused residual add + LayerNorm (in place on g_x) ----------------
__global__ void __launch_bounds__(256)
add_ln_kernel(const float* __restrict__ y,
              const float* __restrict__ gamma, const float* __restrict__ beta) {
    int warp = threadIdx.x >> 5, lane = threadIdx.x & 31;
    size_t row = (size_t)blockIdx.x * 8 + warp;
    float* xr = &g_x[row * Cc];
    const float* yr = &y[row * Cc];
    float v[16];
    float s = 0.f;
    #pragma unroll
    for (int i = 0; i < 16; i++) {
        v[i] = xr[lane + 32*i] + yr[lane + 32*i];
        s += v[i];
    }
    #pragma unroll
    for (int off = 16; off > 0; off >>= 1) s += __shfl_xor_sync(0xFFFFFFFFu, s, off);
    float mu = s * (1.0f / Cc);
    float var = 0.f;
    #pragma unroll
    for (int i = 0; i < 16; i++) { float d = v[i] - mu; var += d * d; }
    #pragma unroll
    for (int off = 16; off > 0; off >>= 1) var += __shfl_xor_sync(0xFFFFFFFFu, var, off);
    var *= (1.0f / Cc);
    float r = rsqrtf(var + 1e-5f);
    #pragma unroll
    for (int i = 0; i < 16; i++) {
        int c = lane + 32*i;
        xr[c] = (v[i] - mu) * r * gamma[c] + beta[c];
    }
}

// ---------------- logits: (NT,512) @ (512,65) + b ---------------------------------
__global__ void __launch_bounds__(256)
logits_kernel(const float* __restrict__ lmw, const float* __restrict__ lmb,
              float* __restrict__ out) {
    __shared__ float As[16][512];
    size_t row0 = (size_t)blockIdx.x * 16;
    for (int i = threadIdx.x; i < 16*512; i += 256)
        As[i >> 9][i & 511] = g_x[(row0 + (i >> 9))*Cc + (i & 511)];
    __syncthreads();
    for (int idx2 = threadIdx.x; idx2 < 16*Vv; idx2 += 256) {
        int r = idx2 / Vv, c = idx2 % Vv;
        float s = lmb[c];
        #pragma unroll 8
        for (int k = 0; k < 512; k++) s += As[r][k] * lmw[k*Vv + c];
        out[(row0 + r)*Vv + c] = s;
    }
}

// ---------------- host launch ------------------------------------------------------
extern "C" void kernel_launch(void* const* d_in, const int* in_sizes, int n_in,
                              void* d_out, int out_size) {
    const int*   idx    = (const int*)  d_in[0];
    const float* tok    = (const float*)d_in[1];
    const float* pos    = (const float*)d_in[2];
    const float* wq     = (const float*)d_in[3];
    const float* wk     = (const float*)d_in[4];
    const float* wv     = (const float*)d_in[5];
    const float* proj_w = (const float*)d_in[6];
    const float* proj_b = (const float*)d_in[7];
    const float* w1     = (const float*)d_in[8];
    const float* b1     = (const float*)d_in[9];
    const float* w2     = (const float*)d_in[10];
    const float* b2     = (const float*)d_in[11];
    const float* ln1g   = (const float*)d_in[12];
    const float* ln1b   = (const float*)d_in[13];
    const float* ln2g   = (const float*)d_in[14];
    const float* ln2b   = (const float*)d_in[15];
    const float* lm_w   = (const float*)d_in[16];
    const float* lm_b   = (const float*)d_in[17];
    float* out = (float*)d_out;

    float *x, *qkv, *ao, *y, *hbuf, *wp;
    cudaGetSymbolAddress((void**)&x,    g_x);
    cudaGetSymbolAddress((void**)&qkv,  g_qkv);
    cudaGetSymbolAddress((void**)&ao,   g_ao);
    cudaGetSymbolAddress((void**)&y,    g_y);
    cudaGetSymbolAddress((void**)&hbuf, g_h);
    cudaGetSymbolAddress((void**)&wp,   g_wpack);

    int nPack = Ll*Cc*3*Cc;
    pack_qkv_kernel<<<(nPack + 255)/256, 256>>>(wq, wk, wv);
    embed_kernel<<<(NT*Cc/4 + 255)/256, 256>>>(idx, tok, pos);

    for (int l = 0; l < Ll; l++) {
        // QKV: (NT,512) @ (512,1536)
        gemm_tf32<<<dim3(3*Cc/128, NT/128), 256>>>(
            x, wp + (size_t)l*Cc*3*Cc, nullptr, qkv, NT, 3*Cc, Cc, 0);
        // attention
        attn_kernel<<<Bb*Hh/4, 128>>>();
        // proj: (NT,512) @ (512,512) + b
        gemm_tf32<<<dim3(Cc/128, NT/128), 256>>>(
            ao, proj_w + (size_t)l*Cc*Cc, proj_b + (size_t)l*Cc, y, NT, Cc, Cc, 0);
        // x = LN(x + y)
        add_ln_kernel<<<NT/8, 256>>>(y, ln1g + (size_t)l*Cc, ln1b + (size_t)l*Cc);
        // MLP up: (NT,512) @ (512,2048) + b, relu
        gemm_tf32<<<dim3(DFFd/128, NT/128), 256>>>(
            x, w1 + (size_t)l*Cc*DFFd, b1 + (size_t)l*DFFd, hbuf, NT, DFFd, Cc, 1);
        // MLP down: (NT,2048) @ (2048,512) + b
        gemm_tf32<<<dim3(Cc/128, NT/128), 256>>>(
            hbuf, w2 + (size_t)l*DFFd*Cc, b2 + (size_t)l*Cc, y, NT, Cc, DFFd, 0);
        // x = LN(x + y)
        add_ln_kernel<<<NT/8, 256>>>(y, ln2g + (size_t)l*Cc, ln2b + (size_t)l*Cc);
    }

    logits_kernel<<<NT/16, 256>>>(lm_w, lm_b, out);
}

// round 4
// speedup vs baseline: 1.0298x; 1.0298x over previous
#include <cuda_runtime.h>
#include <cuda_bf16.h>
#include <mma.h>
#include <math.h>
#include <cstdint>
#include <stdint.h>

using namespace nvcuda;

// Problem dims
#define Bb   8192
#define Tt   8
#define Vv   65
#define Cc   512
#define Hh   8
#define HSs  64
#define Ll   6
#define DFFd 2048
#define NT   (Bb*Tt)   // 65536 tokens

// ---------------- scratch (device globals; no allocation allowed) ----------------
__device__ float g_x[(size_t)NT*Cc];            // activations (tf32-rounded)
__device__ float g_qkv[(size_t)NT*3*Cc];        // q|k|v per token
__device__ float g_ao[(size_t)NT*Cc];           // attention output (tf32-rounded)
__device__ float g_y[(size_t)NT*Cc];            // gemm output (pre-LN, full fp32)
__device__ float g_h[(size_t)NT*DFFd];          // MLP hidden (tf32-rounded)
__device__ float g_wpack[(size_t)Ll*Cc*3*Cc];   // packed qkv weights (tf32)
__device__ float g_wproj[(size_t)Ll*Cc*Cc];     // rounded proj weights
__device__ float g_w1r[(size_t)Ll*Cc*DFFd];     // rounded w1
__device__ float g_w2r[(size_t)Ll*DFFd*Cc];     // rounded w2

__device__ __forceinline__ float tf32r(float x) {
    float y;
    asm("cvt.rna.tf32.f32 %0, %1;" : "=f"(y) : "f"(x));
    return y;
}

__device__ __forceinline__ void cp16(void* smem, const void* gmem) {
    unsigned int s = (unsigned int)__cvta_generic_to_shared(smem);
    asm volatile("cp.async.ca.shared.global [%0], [%1], 16;\n" :: "r"(s), "l"(gmem));
}
#define CP_COMMIT() asm volatile("cp.async.commit_group;\n" ::: "memory")
#define CP_WAIT1()  asm volatile("cp.async.wait_group 1;\n" ::: "memory")

// ---------------- weight repack: wq/wk/wv (L,H,C,HS) -> (L, C, 1536), tf32-rounded
__global__ void pack_qkv_kernel(const float* __restrict__ wq,
                                const float* __restrict__ wk,
                                const float* __restrict__ wv) {
    int i = blockIdx.x * 256 + threadIdx.x;
    if (i >= Ll*Cc*3*Cc) return;
    int col = i % (3*Cc);
    int c   = (i / (3*Cc)) % Cc;
    int l   = i / (3*Cc*Cc);
    const float* src; int j;
    if (col < Cc)        { src = wq; j = col; }
    else if (col < 2*Cc) { src = wk; j = col - Cc; }
    else                 { src = wv; j = col - 2*Cc; }
    int h = j / HSs, d = j % HSs;
    g_wpack[i] = tf32r(src[(((size_t)l*Hh + h)*Cc + c)*HSs + d]);
}

// ---------------- tf32 round-copy for weights --------------------------------------
__global__ void round_copy_kernel(const float* __restrict__ src, float* __restrict__ dst, int n4) {
    int i = blockIdx.x * 256 + threadIdx.x;
    if (i >= n4) return;
    float4 v = ((const float4*)src)[i];
    v.x = tf32r(v.x); v.y = tf32r(v.y); v.z = tf32r(v.z); v.w = tf32r(v.w);
    ((float4*)dst)[i] = v;
}

// ---------------- embedding (output tf32-rounded) ----------------------------------
__global__ void embed_kernel(const int* __restrict__ idx,
                             const float* __restrict__ tok,
                             const float* __restrict__ pos) {
    int i = blockIdx.x * 256 + threadIdx.x;
    if (i >= NT*Cc/4) return;
    int c4 = i % (Cc/4);
    int token = i / (Cc/4);
    int t = token & (Tt-1);
    float4 a = ((const float4*)tok)[(size_t)idx[token]*(Cc/4) + c4];
    float4 p = ((const float4*)pos)[(size_t)t*(Cc/4) + c4];
    ((float4*)g_x)[i] = make_float4(tf32r(a.x+p.x), tf32r(a.y+p.y),
                                    tf32r(a.z+p.z), tf32r(a.w+p.w));
}

// ---------------- TF32 wmma GEMM, cp.async double-buffered -------------------------
// C = A(MxK) @ B(KxN) (+bias); flags: 1=relu, 2=tf32-round output
// A,B must already be tf32-rounded. M%128==0, N%128==0, K%16==0.
#define BM 128
#define BN 128
#define BK 16
#define APAD 20
#define BPAD 132

__global__ void __launch_bounds__(256, 2)
gemm_tf32(const float* __restrict__ A, const float* __restrict__ B,
          const float* __restrict__ bias, float* __restrict__ Cmat,
          int M, int N, int K, int flags)
{
    __shared__ float As[2][BM][APAD];
    __shared__ float Bs[2][BK][BPAD];
    __shared__ float stage[8][16][16];

    int tid  = threadIdx.x;
    int warp = tid >> 5, lane = tid & 31;
    int wm = warp >> 2, wn = warp & 3;          // 2x4 warps; warp tile 64x32
    int bm = blockIdx.y * BM, bn = blockIdx.x * BN;

    wmma::fragment<wmma::accumulator,16,16,8,float> acc[4][2];
    #pragma unroll
    for (int i = 0; i < 4; i++)
        #pragma unroll
        for (int j = 0; j < 2; j++)
            wmma::fill_fragment(acc[i][j], 0.0f);

    int arow = tid >> 2, ac4 = (tid & 3) * 4;   // 128 rows x 4 chunks (2 iters)
    int brow = tid >> 5, bc4 = (tid & 31) * 4;  // 16 rows x 32 chunks (2 iters)

    // prologue: stage 0
    {
        #pragma unroll
        for (int r = 0; r < 2; r++) {
            int row = arow + 64*r;
            cp16(&As[0][row][ac4], &A[(size_t)(bm+row)*K + ac4]);
        }
        #pragma unroll
        for (int r = 0; r < 2; r++) {
            int row = brow + 8*r;
            cp16(&Bs[0][row][bc4], &B[(size_t)row*N + bn + bc4]);
        }
        CP_COMMIT();
    }

    int s = 0;
    for (int k0 = 0; k0 < K; k0 += BK, s ^= 1) {
        // issue next stage
        if (k0 + BK < K) {
            int kn = k0 + BK;
            #pragma unroll
            for (int r = 0; r < 2; r++) {
                int row = arow + 64*r;
                cp16(&As[s^1][row][ac4], &A[(size_t)(bm+row)*K + kn + ac4]);
            }
            #pragma unroll
            for (int r = 0; r < 2; r++) {
                int row = brow + 8*r;
                cp16(&Bs[s^1][row][bc4], &B[(size_t)(kn+row)*N + bn + bc4]);
            }
        }
        CP_COMMIT();
        CP_WAIT1();
        __syncthreads();

        #pragma unroll
        for (int kk = 0; kk < 2; kk++) {
            wmma::fragment<wmma::matrix_a,16,16,8,wmma::precision::tf32,wmma::row_major> af[4];
            wmma::fragment<wmma::matrix_b,16,16,8,wmma::precision::tf32,wmma::row_major> bf[2];
            #pragma unroll
            for (int i = 0; i < 4; i++)
                wmma::load_matrix_sync(af[i], &As[s][wm*64 + i*16][kk*8], APAD);
            #pragma unroll
            for (int j = 0; j < 2; j++)
                wmma::load_matrix_sync(bf[j], &Bs[s][kk*8][wn*32 + j*16], BPAD);
            #pragma unroll
            for (int i = 0; i < 4; i++)
                #pragma unroll
                for (int j = 0; j < 2; j++)
                    wmma::mma_sync(acc[i][j], af[i], bf[j], acc[i][j]);
        }
        __syncthreads();
    }

    // epilogue
    #pragma unroll
    for (int i = 0; i < 4; i++) {
        #pragma unroll
        for (int j = 0; j < 2; j++) {
            wmma::store_matrix_sync(&stage[warp][0][0], acc[i][j], 16, wmma::mem_row_major);
            __syncwarp();
            int grow0 = bm + wm*64 + i*16;
            int gcol0 = bn + wn*32 + j*16;
            #pragma unroll
            for (int e = 0; e < 2; e++) {
                int idx2 = e*32 + lane;
                int r = idx2 >> 2, c4 = (idx2 & 3) * 4;
                float4 v = *(float4*)&stage[warp][r][c4];
                if (bias) {
                    float4 bv = *(const float4*)&bias[gcol0 + c4];
                    v.x += bv.x; v.y += bv.y; v.z += bv.z; v.w += bv.w;
                }
                if (flags & 1) {
                    v.x = fmaxf(v.x, 0.f); v.y = fmaxf(v.y, 0.f);
                    v.z = fmaxf(v.z, 0.f); v.w = fmaxf(v.w, 0.f);
                }
                if (flags & 2) {
                    v.x = tf32r(v.x); v.y = tf32r(v.y);
                    v.z = tf32r(v.z); v.w = tf32r(v.w);
                }
                *(float4*)&Cmat[(size_t)(grow0 + r)*N + gcol0 + c4] = v;
            }
            __syncwarp();
        }
    }
}

// ---------------- attention: one warp per (b,h); T=8, HS=64; scale = C^-0.5 -------
__global__ void __launch_bounds__(128)
attn_kernel() {
    __shared__ float sq[4][8][64], sk[4][8][64], sv[4][8][64];
    __shared__ float satt[4][8][8];
    int warp = threadIdx.x >> 5, lane = threadIdx.x & 31;
    int bh = blockIdx.x * 4 + warp;
    int b = bh >> 3, h = bh & 7;
    size_t tok0 = (size_t)b * Tt;

    #pragma unroll
    for (int t = 0; t < 8; t++) {
        const float2* row2 = (const float2*)&g_qkv[(tok0 + t) * (3*Cc)];
        ((float2*)sq[warp][t])[lane] = row2[h*32 + lane];
        ((float2*)sk[warp][t])[lane] = row2[Cc/2 + h*32 + lane];
        ((float2*)sv[warp][t])[lane] = row2[Cc   + h*32 + lane];
    }
    __syncwarp();

    const float scale = 0.044194173824159216f;   // 512^-0.5
    #pragma unroll
    for (int p = lane; p < 64; p += 32) {
        int t = p >> 3, sIdx = p & 7;
        float acc = 0.f;
        #pragma unroll
        for (int d = 0; d < 64; d++) acc += sq[warp][t][d] * sk[warp][sIdx][d];
        satt[warp][t][sIdx] = (sIdx <= t) ? acc * scale : 0.0f;
    }
    __syncwarp();

    if (lane < 8) {
        int t = lane;
        float m = -1e30f;
        for (int sIdx = 0; sIdx <= t; sIdx++) m = fmaxf(m, satt[warp][t][sIdx]);
        float e[8]; float sum = 0.f;
        #pragma unroll
        for (int sIdx = 0; sIdx < 8; sIdx++) {
            e[sIdx] = (sIdx <= t) ? __expf(satt[warp][t][sIdx] - m) : 0.0f;
            sum += e[sIdx];
        }
        float inv = 1.0f / sum;
        #pragma unroll
        for (int sIdx = 0; sIdx < 8; sIdx++) satt[warp][t][sIdx] = e[sIdx] * inv;
    }
    __syncwarp();

    #pragma unroll
    for (int t = 0; t < 8; t++) {
        float a0 = 0.f, a1 = 0.f;
        #pragma unroll
        for (int sIdx = 0; sIdx < 8; sIdx++) {
            float w = satt[warp][sIdx][0]; // placeholder to keep compiler honest
        }
        a0 = 0.f; a1 = 0.f;
        #pragma unroll
        for (int sIdx = 0; sIdx < 8; sIdx++) {
            float w = satt[warp][t][sIdx];
            a0 += w * sv[warp][sIdx][lane];
            a1 += w * sv[warp][sIdx][lane + 32];
        }
        g_ao[(tok0 + t)*Cc + h*64 + lane]      = tf32r(a0);
        g_ao[(tok0 + t)*Cc + h*64 + lane + 32] = tf32r(a1);
    }
}

// ---------------- fused residual add + LayerNorm (in place on g_x, tf32 out) ------
__global__ void __launch_bounds__(256)
add_ln_kernel(const float* __restrict__ y,
              const float* __restrict__ gamma, const float* __restrict__ beta) {
    int warp = threadIdx.x >> 5, lane = threadIdx.x & 31;
    size_t row = (size_t)blockIdx.x * 8 + warp;
    float* xr = &g_x[row * Cc];
    const float* yr = &y[row * Cc];
    float v[16];
    float s = 0.f;
    #pragma unroll
    for (int i = 0; i < 16; i++) {
        v[i] = xr[lane + 32*i] + yr[lane + 32*i];
        s += v[i];
    }
    #pragma unroll
    for (int off = 16; off > 0; off >>= 1) s += __shfl_xor_sync(0xFFFFFFFFu, s, off);
    float mu = s * (1.0f / Cc);
    float var = 0.f;
    #pragma unroll
    for (int i = 0; i < 16; i++) { float d = v[i] - mu; var += d * d; }
    #pragma unroll
    for (int off = 16; off > 0; off >>= 1) var += __shfl_xor_sync(0xFFFFFFFFu, var, off);
    var *= (1.0f / Cc);
    float r = rsqrtf(var + 1e-5f);
    #pragma unroll
    for (int i = 0; i < 16; i++) {
        int c = lane + 32*i;
        xr[c] = tf32r((v[i] - mu) * r * gamma[c] + beta[c]);
    }
}

// ---------------- logits: (NT,512) @ (512,65) + b ---------------------------------
__global__ void __launch_bounds__(256)
logits_kernel(const float* __restrict__ lmw, const float* __restrict__ lmb,
              float* __restrict__ out) {
    __shared__ float As2[16][512];
    size_t row0 = (size_t)blockIdx.x * 16;
    for (int i = threadIdx.x; i < 16*512; i += 256)
        As2[i >> 9][i & 511] = g_x[(row0 + (i >> 9))*Cc + (i & 511)];
    __syncthreads();
    for (int idx2 = threadIdx.x; idx2 < 16*Vv; idx2 += 256) {
        int r = idx2 / Vv, c = idx2 % Vv;
        float s = lmb[c];
        #pragma unroll 8
        for (int k = 0; k < 512; k++) s += As2[r][k] * lmw[k*Vv + c];
        out[(row0 + r)*Vv + c] = s;
    }
}

// ---------------- host launch ------------------------------------------------------
extern "C" void kernel_launch(void* const* d_in, const int* in_sizes, int n_in,
                              void* d_out, int out_size) {
    const int*   idx    = (const int*)  d_in[0];
    const float* tok    = (const float*)d_in[1];
    const float* pos    = (const float*)d_in[2];
    const float* wq     = (const float*)d_in[3];
    const float* wk     = (const float*)d_in[4];
    const float* wv     = (const float*)d_in[5];
    const float* proj_w = (const float*)d_in[6];
    const float* proj_b = (const float*)d_in[7];
    const float* w1     = (const float*)d_in[8];
    const float* b1     = (const float*)d_in[9];
    const float* w2     = (const float*)d_in[10];
    const float* b2     = (const float*)d_in[11];
    const float* ln1g   = (const float*)d_in[12];
    const float* ln1b   = (const float*)d_in[13];
    const float* ln2g   = (const float*)d_in[14];
    const float* ln2b   = (const float*)d_in[15];
    const float* lm_w   = (const float*)d_in[16];
    const float* lm_b   = (const float*)d_in[17];
    float* out = (float*)d_out;

    float *x, *qkv, *ao, *y, *hbuf, *wp, *wpr, *w1r, *w2r;
    cudaGetSymbolAddress((void**)&x,    g_x);
    cudaGetSymbolAddress((void**)&qkv,  g_qkv);
    cudaGetSymbolAddress((void**)&ao,   g_ao);
    cudaGetSymbolAddress((void**)&y,    g_y);
    cudaGetSymbolAddress((void**)&hbuf, g_h);
    cudaGetSymbolAddress((void**)&wp,   g_wpack);
    cudaGetSymbolAddress((void**)&wpr,  g_wproj);
    cudaGetSymbolAddress((void**)&w1r,  g_w1r);
    cudaGetSymbolAddress((void**)&w2r,  g_w2r);

    int nPack = Ll*Cc*3*Cc;
    pack_qkv_kernel<<<(nPack + 255)/256, 256>>>(wq, wk, wv);
    round_copy_kernel<<<(Ll*Cc*Cc/4 + 255)/256, 256>>>(proj_w, wpr, Ll*Cc*Cc/4);
    round_copy_kernel<<<(Ll*Cc*DFFd/4 + 255)/256, 256>>>(w1, w1r, Ll*Cc*DFFd/4);
    round_copy_kernel<<<(Ll*DFFd*Cc/4 + 255)/256, 256>>>(w2, w2r, Ll*DFFd*Cc/4);
    embed_kernel<<<(NT*Cc/4 + 255)/256, 256>>>(idx, tok, pos);

    for (int l = 0; l < Ll; l++) {
        // QKV: (NT,512) @ (512,1536)
        gemm_tf32<<<dim3(3*Cc/BN, NT/BM), 256>>>(
            x, wp + (size_t)l*Cc*3*Cc, nullptr, qkv, NT, 3*Cc, Cc, 0);
        // attention
        attn_kernel<<<Bb*Hh/4, 128>>>();
        // proj: (NT,512) @ (512,512) + b
        gemm_tf32<<<dim3(Cc/BN, NT/BM), 256>>>(
            ao, wpr + (size_t)l*Cc*Cc, proj_b + (size_t)l*Cc, y, NT, Cc, Cc, 0);
        // x = LN(x + y), tf32 out
        add_ln_kernel<<<NT/8, 256>>>(y, ln1g + (size_t)l*Cc, ln1b + (size_t)l*Cc);
        // MLP up: (NT,512) @ (512,2048) + b, relu, tf32 out
        gemm_tf32<<<dim3(DFFd/BN, NT/BM), 256>>>(
            x, w1r + (size_t)l*Cc*DFFd, b1 + (size_t)l*DFFd, hbuf, NT, DFFd, Cc, 3);
        // MLP down: (NT,2048) @ (2048,512) + b
        gemm_tf32<<<dim3(Cc/BN, NT/BM), 256>>>(
            hbuf, w2r + (size_t)l*DFFd*Cc, b2 + (size_t)l*Cc, y, NT, Cc, DFFd, 0);
        // x = LN(x + y), tf32 out
        add_ln_kernel<<<NT/8, 256>>>(y, ln2g + (size_t)l*Cc, ln2b + (size_t)l*Cc);
    }

    logits_kernel<<<NT/16, 256>>>(lm_w, lm_b, out);
}